// round 8
// baseline (speedup 1.0000x reference)
#include <cuda_runtime.h>

#define BB 64
#define WW 128
#define FF 64
#define OUTF 64
#define CH 128
#define TI 16
#define PARTN (BB * WW * OUTF)

typedef unsigned long long ull;

// Scratch: projected features (with bias), per-head partial outputs
__device__ float g_fsrc[BB * WW * CH];
__device__ float g_fdst[BB * WW * CH];
__device__ float g_part[2 * PARTN];
__device__ unsigned g_cnt[BB * (WW / TI)];   // last-block counters (parity-based)

// ---- packed f32x2 helpers ----
__device__ __forceinline__ ull fma2(ull a, ull b, ull c) {
    ull d; asm("fma.rn.f32x2 %0, %1, %2, %3;" : "=l"(d) : "l"(a), "l"(b), "l"(c)); return d;
}
__device__ __forceinline__ ull add2(ull a, ull b) {
    ull d; asm("add.rn.f32x2 %0, %1, %2;" : "=l"(d) : "l"(a), "l"(b)); return d;
}
__device__ __forceinline__ ull dup2(float a) {
    ull d; asm("mov.b64 %0, {%1, %1};" : "=l"(d) : "f"(a)); return d;
}
__device__ __forceinline__ float lo2(ull v) { return __uint_as_float((unsigned)(v & 0xffffffffu)); }
__device__ __forceinline__ float hi2(ull v) { return __uint_as_float((unsigned)(v >> 32)); }
__device__ __forceinline__ float hsum2(ull v) { return lo2(v) + hi2(v); }
#define ABSMASK 0x7fffffff7fffffffULL

// 16B-chunk swizzle within a 64-float (16-chunk) row
__device__ __forceinline__ int swz16(int row, int c) { return (c & 8) | ((c ^ row) & 7); }

__device__ __forceinline__ unsigned to_tf32(float v) {
    unsigned o; asm("cvt.rna.tf32.f32 %0, %1;" : "=r"(o) : "f"(v)); return o;
}

// ---------------------------------------------------------------------------
// Kernel 1: projections via tf32 tensor cores, 64-row tiles.
// C[8192 x 256] = X[8192 x 64] @ W^T + bias.
// grid (4, 128): bx = (src/dst, 64-col half), by = 64-row tile. 256 thr.
// Warp w: m-rows [16*(w&3), +16), n-cols [32*(w>>2), +32), k = 64.
// ---------------------------------------------------------------------------
#define PROJ_SM_BYTES ((64 * 68 + 64 * 68) * 4)

__global__ __launch_bounds__(256, 4) void proj_kernel(
    const float* __restrict__ x,
    const float* __restrict__ w_src, const float* __restrict__ b_src,
    const float* __restrict__ w_dst, const float* __restrict__ b_dst)
{
    extern __shared__ unsigned psm[];
    unsigned* xs = psm;                 // 64 x 68 (tf32 bits)
    unsigned* ws = psm + 64 * 68;       // 64 x 68

    const int tid = threadIdx.x;
    const int ot = blockIdx.x;           // 0..3
    const int row0 = blockIdx.y * 64;
    const bool is_src = (ot < 2);
    const float* __restrict__ wm = is_src ? w_src : w_dst;
    const float* __restrict__ bv = is_src ? b_src : b_dst;
    const int obase = (ot & 1) * 64;

    // ---- fill (convert to tf32 once) ----
    const float4* __restrict__ x4 = (const float4*)(x + row0 * FF);
    const float4* __restrict__ w4 = (const float4*)(wm + obase * FF);
    #pragma unroll
    for (int t = 0; t < 4; t++) {        // 1024 float4 of x
        int m = tid + 256 * t;
        int r = m >> 4, c4 = m & 15;
        float4 v = x4[m];
        uint4 u;
        u.x = to_tf32(v.x); u.y = to_tf32(v.y);
        u.z = to_tf32(v.z); u.w = to_tf32(v.w);
        *(uint4*)(xs + r * 68 + c4 * 4) = u;
    }
    #pragma unroll
    for (int t = 0; t < 4; t++) {        // 1024 float4 of w
        int m = tid + 256 * t;
        int r = m >> 4, c4 = m & 15;
        float4 v = w4[m];
        uint4 u;
        u.x = to_tf32(v.x); u.y = to_tf32(v.y);
        u.z = to_tf32(v.z); u.w = to_tf32(v.w);
        *(uint4*)(ws + r * 68 + c4 * 4) = u;
    }
    __syncthreads();

    const int w    = tid >> 5;
    const int lane = tid & 31;
    const int ly = lane >> 2;     // 0..7
    const int lx = lane & 3;      // 0..3
    const int m0 = (w & 3) * 16;
    const int n0 = (w >> 2) * 32;

    float acc[4][4];
    #pragma unroll
    for (int t = 0; t < 4; t++)
        #pragma unroll
        for (int q = 0; q < 4; q++) acc[t][q] = 0.0f;

    #pragma unroll
    for (int k0 = 0; k0 < 64; k0 += 8) {
        unsigned a0 = xs[(m0 + ly) * 68 + k0 + lx];
        unsigned a1 = xs[(m0 + ly + 8) * 68 + k0 + lx];
        unsigned a2 = xs[(m0 + ly) * 68 + k0 + lx + 4];
        unsigned a3 = xs[(m0 + ly + 8) * 68 + k0 + lx + 4];
        #pragma unroll
        for (int t = 0; t < 4; t++) {
            unsigned b0 = ws[(n0 + t * 8 + ly) * 68 + k0 + lx];
            unsigned b1 = ws[(n0 + t * 8 + ly) * 68 + k0 + lx + 4];
            asm("mma.sync.aligned.m16n8k8.row.col.f32.tf32.tf32.f32 "
                "{%0,%1,%2,%3}, {%4,%5,%6,%7}, {%8,%9}, {%0,%1,%2,%3};"
                : "+f"(acc[t][0]), "+f"(acc[t][1]), "+f"(acc[t][2]), "+f"(acc[t][3])
                : "r"(a0), "r"(a1), "r"(a2), "r"(a3), "r"(b0), "r"(b1));
        }
    }

    // ---- epilogue: bias + store (STG.64 pairs) ----
    float* __restrict__ dst = is_src ? g_fsrc : g_fdst;
    #pragma unroll
    for (int t = 0; t < 4; t++) {
        int cb = n0 + t * 8 + 2 * lx;            // local col (pair base)
        float2 bias = *(const float2*)(bv + obase + cb);
        int rA = row0 + m0 + ly;
        float2 oA = make_float2(acc[t][0] + bias.x, acc[t][1] + bias.y);
        float2 oB = make_float2(acc[t][2] + bias.x, acc[t][3] + bias.y);
        *(float2*)(dst + rA * CH + obase + cb) = oA;
        *(float2*)(dst + (rA + 8) * CH + obase + cb) = oB;
    }
}

// ---------------------------------------------------------------------------
// Kernel 2: attention, HEAD-SPLIT. grid (8 i-tiles, 64 b, 2 h), 256 threads.
// Score/softmax: warp owns 2 rows, in-warp softmax.
// Aggregation: j-quarter split, 4-f-wide threads, STG to g_part.
// Epilogue: last block per (b, i-tile) combines both heads into out.
// smem (floats):
//   fsrc_h [128 x 64]  swizzled 16B chunks       0 .. 8192
//   fdst_h [16 x 68]   padded                 8192 .. 9280
//   alpha2 [16 x 128]  DUP f32 pairs          9280 .. 13376  (reused as red)
//   a04    [64]                              13376 .. 13440  (reused as flag)
//   sA     [128]                             13440 .. 13568  (1.5-prescaled)
//   dA     [16]                              13568 .. 13584
// ---------------------------------------------------------------------------
#define OFF_FDST  8192
#define OFF_ALPHA 9280
#define OFF_A04   13376
#define OFF_SA    13440
#define OFF_DA    13568
#define SM_FLOATS 13584
#define SM_BYTES  (SM_FLOATS * 4)

__global__ __launch_bounds__(256, 4) void attn_kernel(
    const float* __restrict__ attn_w,
    float* __restrict__ out)
{
    extern __shared__ float sm[];
    float* fsrc_sm = sm;
    float* fdst_sm = sm + OFF_FDST;
    ull*   alpha2  = (ull*)(sm + OFF_ALPHA);
    float* a04     = sm + OFF_A04;
    float* sA      = sm + OFF_SA;
    float* dA      = sm + OFF_DA;

    const int tid = threadIdx.x;
    const int b  = blockIdx.y;
    const int i0 = blockIdx.x * TI;
    const int h  = blockIdx.z;

    ulonglong2* fs16 = (ulonglong2*)fsrc_sm;

    // ---- fill fsrc_h: 128 rows x 16 chunks (swizzled, STS.128) ----
    {
        const float4* __restrict__ g4 = (const float4*)(g_fsrc + b * WW * CH + h * 64);
        #pragma unroll
        for (int t = 0; t < 8; t++) {
            int m = tid + 256 * t;           // 2048 chunks
            int j = m >> 4, c = m & 15;
            float4 v = g4[j * 32 + c];
            *(float4*)(fsrc_sm + j * 64 + swz16(j, c) * 4) = v;
        }
    }
    // ---- fill fdst_h tile: 16 rows x 16 chunks, padded stride 68 ----
    {
        const float4* __restrict__ g4 = (const float4*)(g_fdst + (b * WW + i0) * CH + h * 64);
        int i = tid >> 4, c = tid & 15;
        *(float4*)(fdst_sm + i * 68 + c * 4) = g4[i * 32 + c];
    }
    if (tid < 64) a04[tid] = 0.4f * attn_w[h * 64 + tid];
    __syncthreads();

    // ---- per-node dots (1.5-prescaled linear leakyrelu component) ----
    if (tid < 128) {               // sA[j]
        int j = tid;
        const ulonglong2* a16 = (const ulonglong2*)a04;
        ull acc = 0ULL;
        #pragma unroll
        for (int f4 = 0; f4 < 16; f4++) {
            ulonglong2 sv = fs16[j * 16 + swz16(j, f4)];
            ulonglong2 av = a16[f4];
            acc = fma2(av.x, sv.x, acc);
            acc = fma2(av.y, sv.y, acc);
        }
        sA[j] = 1.5f * hsum2(acc);
    } else if (tid < 144) {        // dA[i]
        int il = tid - 128;
        const ulonglong2* d16 = (const ulonglong2*)(fdst_sm + il * 68);
        const ulonglong2* a16 = (const ulonglong2*)a04;
        ull acc = 0ULL;
        #pragma unroll
        for (int f4 = 0; f4 < 16; f4++) {
            ulonglong2 dv = d16[f4];
            ulonglong2 av = a16[f4];
            acc = fma2(av.x, dv.x, acc);
            acc = fma2(av.y, dv.y, acc);
        }
        dA[il] = 1.5f * hsum2(acc);
    }
    __syncthreads();

    // ---- score: warp w owns i rows {w, w+8}; lanes jt; j = jt + 32c ----
    const int jt = tid & 31;
    const int w  = tid >> 5;

    ull acc2[2][4];
    #pragma unroll
    for (int r = 0; r < 2; r++)
        #pragma unroll
        for (int c = 0; c < 4; c++) acc2[r][c] = 0ULL;

    {
        const ulonglong2* a16 = (const ulonglong2*)a04;
        #pragma unroll 4
        for (int f4 = 0; f4 < 16; f4++) {
            ulonglong2 av = a16[f4];
            ulonglong2 dv[2], sv[4];
            dv[0] = *(const ulonglong2*)(fdst_sm + w * 68 + f4 * 4);
            dv[1] = *(const ulonglong2*)(fdst_sm + (w + 8) * 68 + f4 * 4);
            int cs = swz16(jt, f4);
            #pragma unroll
            for (int c = 0; c < 4; c++)
                sv[c] = fs16[(jt + 32 * c) * 16 + cs];
            #pragma unroll
            for (int r = 0; r < 2; r++)
                #pragma unroll
                for (int c = 0; c < 4; c++) {
                    ull t0 = add2(sv[c].x, dv[r].x) & ABSMASK;
                    acc2[r][c] = fma2(av.x, t0, acc2[r][c]);
                    ull t1 = add2(sv[c].y, dv[r].y) & ABSMASK;
                    acc2[r][c] = fma2(av.y, t1, acc2[r][c]);
                }
        }
    }

    // ---- softmax over j (in-warp), write DUPLICATED alpha pairs ----
    {
        float sAv[4];
        #pragma unroll
        for (int c = 0; c < 4; c++) sAv[c] = sA[jt + 32 * c];

        #pragma unroll
        for (int r = 0; r < 2; r++) {
            int il = w + 8 * r;
            float dv = dA[il];
            float e[4];
            #pragma unroll
            for (int c = 0; c < 4; c++)
                e[c] = sAv[c] + dv + hsum2(acc2[r][c]);

            float m = fmaxf(fmaxf(e[0], e[1]), fmaxf(e[2], e[3]));
            #pragma unroll
            for (int off = 16; off > 0; off >>= 1)
                m = fmaxf(m, __shfl_xor_sync(0xffffffffu, m, off));

            float p[4], ssum = 0.0f;
            #pragma unroll
            for (int c = 0; c < 4; c++) { p[c] = __expf(e[c] - m); ssum += p[c]; }
            #pragma unroll
            for (int off = 16; off > 0; off >>= 1)
                ssum += __shfl_xor_sync(0xffffffffu, ssum, off);

            float inv = 1.0f / ssum;
            #pragma unroll
            for (int c = 0; c < 4; c++)
                alpha2[il * WW + jt + 32 * c] = dup2(p[c] * inv);
        }
    }
    __syncthreads();

    // ---- aggregation: js = j-quarter, ig -> i rows {ig+4k}, fg = 4-float group
    const int fg = tid & 15;
    const int ig = (tid >> 4) & 3;
    const int js = tid >> 6;

    ull accA[4][2];
    #pragma unroll
    for (int k = 0; k < 4; k++) { accA[k][0] = 0ULL; accA[k][1] = 0ULL; }

    {
        const ulonglong2* A2 = (const ulonglong2*)alpha2;   // [row][64 j-pairs]
        #pragma unroll 4
        for (int jp = 0; jp < 16; jp++) {
            int jp2 = js * 16 + jp;
            int ja = 2 * jp2, jb = ja + 1;
            ulonglong2 al[4];
            #pragma unroll
            for (int k = 0; k < 4; k++)
                al[k] = A2[(ig + 4 * k) * 64 + jp2];        // 2 addrs/warp
            ulonglong2 s0 = fs16[ja * 16 + swz16(ja, fg)];  // 4 floats of row ja
            ulonglong2 s1 = fs16[jb * 16 + swz16(jb, fg)];
            #pragma unroll
            for (int k = 0; k < 4; k++) {
                accA[k][0] = fma2(al[k].x, s0.x, accA[k][0]);
                accA[k][1] = fma2(al[k].x, s0.y, accA[k][1]);
                accA[k][0] = fma2(al[k].y, s1.x, accA[k][0]);
                accA[k][1] = fma2(al[k].y, s1.y, accA[k][1]);
            }
        }
    }

    // ---- cross-quarter reduction (scratch reuses alpha region) + STG ----
    __syncthreads();                    // all alpha/fsrc reads done
    {
        ull* red = (ull*)alpha2;        // 2048 ull available; need 192*9=1728
        const int t64 = tid & 63;
        if (js > 0) {
            int base = ((js - 1) * 64 + t64) * 9;   // stride 9 -> low conflict
            #pragma unroll
            for (int k = 0; k < 4; k++) {
                red[base + 2 * k]     = accA[k][0];
                red[base + 2 * k + 1] = accA[k][1];
            }
        }
        __syncthreads();
        if (js == 0) {
            float* part = g_part + h * PARTN;
            #pragma unroll
            for (int q = 1; q < 4; q++) {
                const ull* rr = red + ((q - 1) * 64 + t64) * 9;
                #pragma unroll
                for (int k = 0; k < 4; k++) {
                    accA[k][0] = add2(accA[k][0], rr[2 * k]);
                    accA[k][1] = add2(accA[k][1], rr[2 * k + 1]);
                }
            }
            #pragma unroll
            for (int k = 0; k < 4; k++) {
                int i = i0 + ig + 4 * k;
                float4 o;
                o.x = lo2(accA[k][0]); o.y = hi2(accA[k][0]);
                o.z = lo2(accA[k][1]); o.w = hi2(accA[k][1]);
                *(float4*)(part + (b * WW + i) * OUTF + fg * 4) = o;
            }
        }
    }

    // ---- last block per (b, i-tile) combines both heads into out ----
    __syncthreads();                    // part-tile writes issued by all js==0
    {
        unsigned* flag = (unsigned*)a04;
        if (tid == 0) {
            __threadfence();            // release: part tile visible
            unsigned old = atomicAdd(&g_cnt[b * (WW / TI) + blockIdx.x], 1u);
            flag[0] = old;
        }
        __syncthreads();
        if (flag[0] & 1u) {             // second arriver (parity-safe across replays)
            __threadfence();            // acquire: peer's part tile visible
            int base4 = (b * WW + i0) * OUTF / 4;   // 256 float4 tile
            const float4* p0 = (const float4*)g_part + base4;
            const float4* p1 = (const float4*)(g_part + PARTN) + base4;
            float4 A = p0[tid], C = p1[tid];
            float4 o;
            o.x = 0.5f * (A.x + C.x);
            o.y = 0.5f * (A.y + C.y);
            o.z = 0.5f * (A.z + C.z);
            o.w = 0.5f * (A.w + C.w);
            ((float4*)out)[base4 + tid] = o;
        }
    }
}

// ---------------------------------------------------------------------------
extern "C" void kernel_launch(void* const* d_in, const int* in_sizes, int n_in,
                              void* d_out, int out_size)
{
    (void)in_sizes; (void)n_in; (void)out_size;
    const float* x      = (const float*)d_in[0];
    const float* w_src  = (const float*)d_in[1];
    const float* b_src  = (const float*)d_in[2];
    const float* w_dst  = (const float*)d_in[3];
    const float* b_dst  = (const float*)d_in[4];
    const float* attn_w = (const float*)d_in[5];
    float* out = (float*)d_out;

    cudaFuncSetAttribute(proj_kernel,
                         cudaFuncAttributeMaxDynamicSharedMemorySize,
                         PROJ_SM_BYTES);
    cudaFuncSetAttribute(attn_kernel,
                         cudaFuncAttributeMaxDynamicSharedMemorySize,
                         SM_BYTES);

    proj_kernel<<<dim3(4, 128), 256, PROJ_SM_BYTES>>>(x, w_src, b_src, w_dst, b_dst);
    attn_kernel<<<dim3(WW / TI, BB, 2), 256, SM_BYTES>>>(attn_w, out);
}

// round 9
// speedup vs baseline: 1.0008x; 1.0008x over previous
#include <cuda_runtime.h>

#define BB 64
#define WW 128
#define FF 64
#define OUTF 64
#define CH 128
#define TI 16
#define PARTN (BB * WW * OUTF)

typedef unsigned long long ull;

// Scratch: projected features (with bias), per-head partial outputs
__device__ float g_fsrc[BB * WW * CH];
__device__ float g_fdst[BB * WW * CH];
__device__ float g_part[2 * PARTN];

// ---- packed f32x2 helpers ----
__device__ __forceinline__ ull fma2(ull a, ull b, ull c) {
    ull d; asm("fma.rn.f32x2 %0, %1, %2, %3;" : "=l"(d) : "l"(a), "l"(b), "l"(c)); return d;
}
__device__ __forceinline__ ull add2(ull a, ull b) {
    ull d; asm("add.rn.f32x2 %0, %1, %2;" : "=l"(d) : "l"(a), "l"(b)); return d;
}
__device__ __forceinline__ ull dup2(float a) {
    ull d; asm("mov.b64 %0, {%1, %1};" : "=l"(d) : "f"(a)); return d;
}
__device__ __forceinline__ float lo2(ull v) { return __uint_as_float((unsigned)(v & 0xffffffffu)); }
__device__ __forceinline__ float hi2(ull v) { return __uint_as_float((unsigned)(v >> 32)); }
__device__ __forceinline__ float hsum2(ull v) { return lo2(v) + hi2(v); }
#define ABSMASK 0x7fffffff7fffffffULL

// 16B-chunk swizzle within a 64-float (16-chunk) row
__device__ __forceinline__ int swz16(int row, int c) { return (c & 8) | ((c ^ row) & 7); }

__device__ __forceinline__ unsigned to_tf32(float v) {
    unsigned o; asm("cvt.rna.tf32.f32 %0, %1;" : "=r"(o) : "f"(v)); return o;
}

// ---------------------------------------------------------------------------
// Kernel 1: projections via tf32 tensor cores, 64-row tiles.
// C[8192 x 256] = X[8192 x 64] @ W^T + bias.
// grid (4, 128): bx = (src/dst, 64-col half), by = 64-row tile. 256 thr.
// Warp w: m-rows [16*(w&3), +16), n-cols [32*(w>>2), +32), k = 64.
// ---------------------------------------------------------------------------
#define PROJ_SM_BYTES ((64 * 68 + 64 * 68) * 4)

__global__ __launch_bounds__(256, 4) void proj_kernel(
    const float* __restrict__ x,
    const float* __restrict__ w_src, const float* __restrict__ b_src,
    const float* __restrict__ w_dst, const float* __restrict__ b_dst)
{
    extern __shared__ unsigned psm[];
    unsigned* xs = psm;                 // 64 x 68 (tf32 bits)
    unsigned* ws = psm + 64 * 68;       // 64 x 68

    const int tid = threadIdx.x;
    const int ot = blockIdx.x;           // 0..3
    const int row0 = blockIdx.y * 64;
    const bool is_src = (ot < 2);
    const float* __restrict__ wm = is_src ? w_src : w_dst;
    const float* __restrict__ bv = is_src ? b_src : b_dst;
    const int obase = (ot & 1) * 64;

    // ---- fill (convert to tf32 once) ----
    const float4* __restrict__ x4 = (const float4*)(x + row0 * FF);
    const float4* __restrict__ w4 = (const float4*)(wm + obase * FF);
    #pragma unroll
    for (int t = 0; t < 4; t++) {        // 1024 float4 of x
        int m = tid + 256 * t;
        int r = m >> 4, c4 = m & 15;
        float4 v = x4[m];
        uint4 u;
        u.x = to_tf32(v.x); u.y = to_tf32(v.y);
        u.z = to_tf32(v.z); u.w = to_tf32(v.w);
        *(uint4*)(xs + r * 68 + c4 * 4) = u;
    }
    #pragma unroll
    for (int t = 0; t < 4; t++) {        // 1024 float4 of w
        int m = tid + 256 * t;
        int r = m >> 4, c4 = m & 15;
        float4 v = w4[m];
        uint4 u;
        u.x = to_tf32(v.x); u.y = to_tf32(v.y);
        u.z = to_tf32(v.z); u.w = to_tf32(v.w);
        *(uint4*)(ws + r * 68 + c4 * 4) = u;
    }
    __syncthreads();

    const int w    = tid >> 5;
    const int lane = tid & 31;
    const int ly = lane >> 2;     // 0..7
    const int lx = lane & 3;      // 0..3
    const int m0 = (w & 3) * 16;
    const int n0 = (w >> 2) * 32;

    float acc[4][4];
    #pragma unroll
    for (int t = 0; t < 4; t++)
        #pragma unroll
        for (int q = 0; q < 4; q++) acc[t][q] = 0.0f;

    #pragma unroll
    for (int k0 = 0; k0 < 64; k0 += 8) {
        unsigned a0 = xs[(m0 + ly) * 68 + k0 + lx];
        unsigned a1 = xs[(m0 + ly + 8) * 68 + k0 + lx];
        unsigned a2 = xs[(m0 + ly) * 68 + k0 + lx + 4];
        unsigned a3 = xs[(m0 + ly + 8) * 68 + k0 + lx + 4];
        #pragma unroll
        for (int t = 0; t < 4; t++) {
            unsigned b0 = ws[(n0 + t * 8 + ly) * 68 + k0 + lx];
            unsigned b1 = ws[(n0 + t * 8 + ly) * 68 + k0 + lx + 4];
            asm("mma.sync.aligned.m16n8k8.row.col.f32.tf32.tf32.f32 "
                "{%0,%1,%2,%3}, {%4,%5,%6,%7}, {%8,%9}, {%0,%1,%2,%3};"
                : "+f"(acc[t][0]), "+f"(acc[t][1]), "+f"(acc[t][2]), "+f"(acc[t][3])
                : "r"(a0), "r"(a1), "r"(a2), "r"(a3), "r"(b0), "r"(b1));
        }
    }

    // ---- epilogue: bias + store (STG.64 pairs) ----
    float* __restrict__ dst = is_src ? g_fsrc : g_fdst;
    #pragma unroll
    for (int t = 0; t < 4; t++) {
        int cb = n0 + t * 8 + 2 * lx;            // local col (pair base)
        float2 bias = *(const float2*)(bv + obase + cb);
        int rA = row0 + m0 + ly;
        float2 oA = make_float2(acc[t][0] + bias.x, acc[t][1] + bias.y);
        float2 oB = make_float2(acc[t][2] + bias.x, acc[t][3] + bias.y);
        *(float2*)(dst + rA * CH + obase + cb) = oA;
        *(float2*)(dst + (rA + 8) * CH + obase + cb) = oB;
    }
}

// ---------------------------------------------------------------------------
// Kernel 2: attention, HEAD-SPLIT. grid (8 i-tiles, 64 b, 2 h), 256 threads.
// Score/softmax: warp owns 2 rows, in-warp softmax (no max-sub; e bounded).
// Aggregation: j-quarter split, 4-f-wide threads, STG to g_part.
// smem (floats):
//   fsrc_h [128 x 64]  swizzled 16B chunks       0 .. 8192
//   fdst_h [16 x 68]   padded                 8192 .. 9280
//   alpha2 [16 x 128]  DUP f32 pairs          9280 .. 13376  (reused as red)
//   a04    [64]                              13376 .. 13440
//   sA     [128]                             13440 .. 13568  (1.5-prescaled)
//   dA     [16]                              13568 .. 13584
// ---------------------------------------------------------------------------
#define OFF_FDST  8192
#define OFF_ALPHA 9280
#define OFF_A04   13376
#define OFF_SA    13440
#define OFF_DA    13568
#define SM_FLOATS 13584
#define SM_BYTES  (SM_FLOATS * 4)

__global__ __launch_bounds__(256, 4) void attn_kernel(const float* __restrict__ attn_w)
{
    extern __shared__ float sm[];
    float* fsrc_sm = sm;
    float* fdst_sm = sm + OFF_FDST;
    ull*   alpha2  = (ull*)(sm + OFF_ALPHA);
    float* a04     = sm + OFF_A04;
    float* sA      = sm + OFF_SA;
    float* dA      = sm + OFF_DA;

    const int tid = threadIdx.x;
    const int b  = blockIdx.y;
    const int i0 = blockIdx.x * TI;
    const int h  = blockIdx.z;

    ulonglong2* fs16 = (ulonglong2*)fsrc_sm;

    // ---- fill fsrc_h: 128 rows x 16 chunks (swizzled, STS.128) ----
    {
        const float4* __restrict__ g4 = (const float4*)(g_fsrc + b * WW * CH + h * 64);
        #pragma unroll
        for (int t = 0; t < 8; t++) {
            int m = tid + 256 * t;           // 2048 chunks
            int j = m >> 4, c = m & 15;
            float4 v = g4[j * 32 + c];
            *(float4*)(fsrc_sm + j * 64 + swz16(j, c) * 4) = v;
        }
    }
    // ---- fill fdst_h tile: 16 rows x 16 chunks, padded stride 68 ----
    {
        const float4* __restrict__ g4 = (const float4*)(g_fdst + (b * WW + i0) * CH + h * 64);
        int i = tid >> 4, c = tid & 15;
        *(float4*)(fdst_sm + i * 68 + c * 4) = g4[i * 32 + c];
    }
    if (tid < 64) a04[tid] = 0.4f * attn_w[h * 64 + tid];
    __syncthreads();

    // ---- per-node dots (1.5-prescaled linear leakyrelu component) ----
    if (tid < 128) {               // sA[j]
        int j = tid;
        const ulonglong2* a16 = (const ulonglong2*)a04;
        ull acc = 0ULL;
        #pragma unroll
        for (int f4 = 0; f4 < 16; f4++) {
            ulonglong2 sv = fs16[j * 16 + swz16(j, f4)];
            ulonglong2 av = a16[f4];
            acc = fma2(av.x, sv.x, acc);
            acc = fma2(av.y, sv.y, acc);
        }
        sA[j] = 1.5f * hsum2(acc);
    } else if (tid < 144) {        // dA[i]
        int il = tid - 128;
        const ulonglong2* d16 = (const ulonglong2*)(fdst_sm + il * 68);
        const ulonglong2* a16 = (const ulonglong2*)a04;
        ull acc = 0ULL;
        #pragma unroll
        for (int f4 = 0; f4 < 16; f4++) {
            ulonglong2 dv = d16[f4];
            ulonglong2 av = a16[f4];
            acc = fma2(av.x, dv.x, acc);
            acc = fma2(av.y, dv.y, acc);
        }
        dA[il] = 1.5f * hsum2(acc);
    }
    __syncthreads();

    // ---- score: warp w owns i rows {w, w+8}; lanes jt; j = jt + 32c ----
    const int jt = tid & 31;
    const int w  = tid >> 5;

    ull acc2[2][4];
    #pragma unroll
    for (int r = 0; r < 2; r++)
        #pragma unroll
        for (int c = 0; c < 4; c++) acc2[r][c] = 0ULL;

    {
        const ulonglong2* a16 = (const ulonglong2*)a04;
        #pragma unroll 4
        for (int f4 = 0; f4 < 16; f4++) {
            ulonglong2 av = a16[f4];
            ulonglong2 dv[2], sv[4];
            dv[0] = *(const ulonglong2*)(fdst_sm + w * 68 + f4 * 4);
            dv[1] = *(const ulonglong2*)(fdst_sm + (w + 8) * 68 + f4 * 4);
            int cs = swz16(jt, f4);
            #pragma unroll
            for (int c = 0; c < 4; c++)
                sv[c] = fs16[(jt + 32 * c) * 16 + cs];
            #pragma unroll
            for (int r = 0; r < 2; r++)
                #pragma unroll
                for (int c = 0; c < 4; c++) {
                    ull t0 = add2(sv[c].x, dv[r].x) & ABSMASK;
                    acc2[r][c] = fma2(av.x, t0, acc2[r][c]);
                    ull t1 = add2(sv[c].y, dv[r].y) & ABSMASK;
                    acc2[r][c] = fma2(av.y, t1, acc2[r][c]);
                }
        }
    }

    // ---- softmax over j (in-warp, no max-sub: |e| <~ 25 << 88) ----
    {
        float sAv[4];
        #pragma unroll
        for (int c = 0; c < 4; c++) sAv[c] = sA[jt + 32 * c];

        #pragma unroll
        for (int r = 0; r < 2; r++) {
            int il = w + 8 * r;
            float dv = dA[il];
            float p[4], ssum = 0.0f;
            #pragma unroll
            for (int c = 0; c < 4; c++) {
                p[c] = __expf(sAv[c] + dv + hsum2(acc2[r][c]));
                ssum += p[c];
            }
            #pragma unroll
            for (int off = 16; off > 0; off >>= 1)
                ssum += __shfl_xor_sync(0xffffffffu, ssum, off);

            float inv = 1.0f / ssum;
            #pragma unroll
            for (int c = 0; c < 4; c++)
                alpha2[il * WW + jt + 32 * c] = dup2(p[c] * inv);
        }
    }
    __syncthreads();

    // ---- aggregation: js = j-quarter, ig -> i rows {ig+4k}, fg = 4-float group
    const int fg = tid & 15;
    const int ig = (tid >> 4) & 3;
    const int js = tid >> 6;

    ull accA[4][2];
    #pragma unroll
    for (int k = 0; k < 4; k++) { accA[k][0] = 0ULL; accA[k][1] = 0ULL; }

    {
        const ulonglong2* A2 = (const ulonglong2*)alpha2;   // [row][64 j-pairs]
        #pragma unroll 4
        for (int jp = 0; jp < 16; jp++) {
            int jp2 = js * 16 + jp;
            int ja = 2 * jp2, jb = ja + 1;
            ulonglong2 al[4];
            #pragma unroll
            for (int k = 0; k < 4; k++)
                al[k] = A2[(ig + 4 * k) * 64 + jp2];        // 2 addrs/warp
            ulonglong2 s0 = fs16[ja * 16 + swz16(ja, fg)];  // 4 floats of row ja
            ulonglong2 s1 = fs16[jb * 16 + swz16(jb, fg)];
            #pragma unroll
            for (int k = 0; k < 4; k++) {
                accA[k][0] = fma2(al[k].x, s0.x, accA[k][0]);
                accA[k][1] = fma2(al[k].x, s0.y, accA[k][1]);
                accA[k][0] = fma2(al[k].y, s1.x, accA[k][0]);
                accA[k][1] = fma2(al[k].y, s1.y, accA[k][1]);
            }
        }
    }

    // ---- cross-quarter reduction (scratch reuses alpha region) + STG ----
    __syncthreads();                    // all alpha/fsrc reads done
    {
        ull* red = (ull*)alpha2;        // 2048 ull available; need 192*9=1728
        const int t64 = tid & 63;
        if (js > 0) {
            int base = ((js - 1) * 64 + t64) * 9;   // stride 9 -> low conflict
            #pragma unroll
            for (int k = 0; k < 4; k++) {
                red[base + 2 * k]     = accA[k][0];
                red[base + 2 * k + 1] = accA[k][1];
            }
        }
        __syncthreads();
        if (js == 0) {
            float* part = g_part + h * PARTN;
            #pragma unroll
            for (int q = 1; q < 4; q++) {
                const ull* rr = red + ((q - 1) * 64 + t64) * 9;
                #pragma unroll
                for (int k = 0; k < 4; k++) {
                    accA[k][0] = add2(accA[k][0], rr[2 * k]);
                    accA[k][1] = add2(accA[k][1], rr[2 * k + 1]);
                }
            }
            #pragma unroll
            for (int k = 0; k < 4; k++) {
                int i = i0 + ig + 4 * k;
                float4 o;
                o.x = lo2(accA[k][0]); o.y = hi2(accA[k][0]);
                o.z = lo2(accA[k][1]); o.w = hi2(accA[k][1]);
                *(float4*)(part + (b * WW + i) * OUTF + fg * 4) = o;
            }
        }
    }
}

// ---------------------------------------------------------------------------
// Kernel 3: combine heads. out = 0.5 * (part0 + part1). 512 x 256 float4.
// ---------------------------------------------------------------------------
__global__ __launch_bounds__(256) void combine_kernel(float* __restrict__ out)
{
    int m = blockIdx.x * 256 + threadIdx.x;
    const float4* p0 = (const float4*)g_part;
    const float4* p1 = (const float4*)(g_part + PARTN);
    float4 a = p0[m], c = p1[m];
    float4 o;
    o.x = 0.5f * (a.x + c.x);
    o.y = 0.5f * (a.y + c.y);
    o.z = 0.5f * (a.z + c.z);
    o.w = 0.5f * (a.w + c.w);
    ((float4*)out)[m] = o;
}

// ---------------------------------------------------------------------------
extern "C" void kernel_launch(void* const* d_in, const int* in_sizes, int n_in,
                              void* d_out, int out_size)
{
    (void)in_sizes; (void)n_in; (void)out_size;
    const float* x      = (const float*)d_in[0];
    const float* w_src  = (const float*)d_in[1];
    const float* b_src  = (const float*)d_in[2];
    const float* w_dst  = (const float*)d_in[3];
    const float* b_dst  = (const float*)d_in[4];
    const float* attn_w = (const float*)d_in[5];
    float* out = (float*)d_out;

    cudaFuncSetAttribute(proj_kernel,
                         cudaFuncAttributeMaxDynamicSharedMemorySize,
                         PROJ_SM_BYTES);
    cudaFuncSetAttribute(attn_kernel,
                         cudaFuncAttributeMaxDynamicSharedMemorySize,
                         SM_BYTES);

    proj_kernel<<<dim3(4, 128), 256, PROJ_SM_BYTES>>>(x, w_src, b_src, w_dst, b_dst);
    attn_kernel<<<dim3(WW / TI, BB, 2), 256, SM_BYTES>>>(attn_w);
    combine_kernel<<<512, 256>>>(out);
}

// round 10
// speedup vs baseline: 1.1101x; 1.1092x over previous
#include <cuda_runtime.h>

#define BB 64
#define WW 128
#define FF 64
#define OUTF 64
#define CH 128
#define TI 16
#define PARTN (BB * WW * OUTF)

typedef unsigned long long ull;

// Scratch: projected features (with bias), per-head partial outputs
__device__ float g_fsrc[BB * WW * CH];
__device__ float g_fdst[BB * WW * CH];
__device__ float g_part[2 * PARTN];

// ---- packed f32x2 helpers ----
__device__ __forceinline__ ull fma2(ull a, ull b, ull c) {
    ull d; asm("fma.rn.f32x2 %0, %1, %2, %3;" : "=l"(d) : "l"(a), "l"(b), "l"(c)); return d;
}
__device__ __forceinline__ ull add2(ull a, ull b) {
    ull d; asm("add.rn.f32x2 %0, %1, %2;" : "=l"(d) : "l"(a), "l"(b)); return d;
}
__device__ __forceinline__ float lo2(ull v) { return __uint_as_float((unsigned)(v & 0xffffffffu)); }
__device__ __forceinline__ float hi2(ull v) { return __uint_as_float((unsigned)(v >> 32)); }
__device__ __forceinline__ float hsum2(ull v) { return lo2(v) + hi2(v); }
#define ABSMASK 0x7fffffff7fffffffULL

// 16B-chunk swizzle within a 64-float (16-chunk) row
__device__ __forceinline__ int swz16(int row, int c) { return (c & 8) | ((c ^ row) & 7); }

__device__ __forceinline__ unsigned to_tf32(float v) {
    unsigned o; asm("cvt.rna.tf32.f32 %0, %1;" : "=r"(o) : "f"(v)); return o;
}

// ---------------------------------------------------------------------------
// Kernel 1: projections via tf32 tensor cores, 32-row tiles.
// C[8192 x 256] = X[8192 x 64] @ W^T + bias.
// grid (4, 256): bx = (src/dst, 64-col half), by = 32-row tile. 256 thr.
// Warp w: m-rows [16*(w&1), +16), n-cols [16*(w>>1), +16), k = 64.
// ---------------------------------------------------------------------------
#define PROJ_SM_BYTES ((32 * 68 + 64 * 68) * 4)

__global__ __launch_bounds__(256, 4) void proj_kernel(
    const float* __restrict__ x,
    const float* __restrict__ w_src, const float* __restrict__ b_src,
    const float* __restrict__ w_dst, const float* __restrict__ b_dst)
{
    extern __shared__ unsigned psm[];
    unsigned* xs = psm;                 // 32 x 68 (tf32 bits)
    unsigned* ws = psm + 32 * 68;       // 64 x 68

    const int tid = threadIdx.x;
    const int ot = blockIdx.x;           // 0..3
    const int row0 = blockIdx.y * 32;
    const bool is_src = (ot < 2);
    const float* __restrict__ wm = is_src ? w_src : w_dst;
    const float* __restrict__ bv = is_src ? b_src : b_dst;
    const int obase = (ot & 1) * 64;

    // ---- fill (convert to tf32 once) ----
    const float4* __restrict__ x4 = (const float4*)(x + row0 * FF);
    const float4* __restrict__ w4 = (const float4*)(wm + obase * FF);
    #pragma unroll
    for (int t = 0; t < 2; t++) {        // 512 float4 of x
        int m = tid + 256 * t;
        int r = m >> 4, c4 = m & 15;
        float4 v = x4[m];
        uint4 u;
        u.x = to_tf32(v.x); u.y = to_tf32(v.y);
        u.z = to_tf32(v.z); u.w = to_tf32(v.w);
        *(uint4*)(xs + r * 68 + c4 * 4) = u;
    }
    #pragma unroll
    for (int t = 0; t < 4; t++) {        // 1024 float4 of w
        int m = tid + 256 * t;
        int r = m >> 4, c4 = m & 15;
        float4 v = w4[m];
        uint4 u;
        u.x = to_tf32(v.x); u.y = to_tf32(v.y);
        u.z = to_tf32(v.z); u.w = to_tf32(v.w);
        *(uint4*)(ws + r * 68 + c4 * 4) = u;
    }
    __syncthreads();

    const int w    = tid >> 5;
    const int lane = tid & 31;
    const int ly = lane >> 2;     // 0..7
    const int lx = lane & 3;      // 0..3
    const int m0 = (w & 1) * 16;
    const int n0 = (w >> 1) * 16;

    float acc[2][4];
    #pragma unroll
    for (int t = 0; t < 2; t++)
        #pragma unroll
        for (int q = 0; q < 4; q++) acc[t][q] = 0.0f;

    #pragma unroll
    for (int k0 = 0; k0 < 64; k0 += 8) {
        unsigned a0 = xs[(m0 + ly) * 68 + k0 + lx];
        unsigned a1 = xs[(m0 + ly + 8) * 68 + k0 + lx];
        unsigned a2 = xs[(m0 + ly) * 68 + k0 + lx + 4];
        unsigned a3 = xs[(m0 + ly + 8) * 68 + k0 + lx + 4];
        #pragma unroll
        for (int t = 0; t < 2; t++) {
            unsigned b0 = ws[(n0 + t * 8 + ly) * 68 + k0 + lx];
            unsigned b1 = ws[(n0 + t * 8 + ly) * 68 + k0 + lx + 4];
            asm("mma.sync.aligned.m16n8k8.row.col.f32.tf32.tf32.f32 "
                "{%0,%1,%2,%3}, {%4,%5,%6,%7}, {%8,%9}, {%0,%1,%2,%3};"
                : "+f"(acc[t][0]), "+f"(acc[t][1]), "+f"(acc[t][2]), "+f"(acc[t][3])
                : "r"(a0), "r"(a1), "r"(a2), "r"(a3), "r"(b0), "r"(b1));
        }
    }

    // ---- epilogue: bias + store (STG.64 pairs) ----
    float* __restrict__ dst = is_src ? g_fsrc : g_fdst;
    #pragma unroll
    for (int t = 0; t < 2; t++) {
        int cb = n0 + t * 8 + 2 * lx;            // local col (pair base)
        float2 bias = *(const float2*)(bv + obase + cb);
        int rA = row0 + m0 + ly;
        float2 oA = make_float2(acc[t][0] + bias.x, acc[t][1] + bias.y);
        float2 oB = make_float2(acc[t][2] + bias.x, acc[t][3] + bias.y);
        *(float2*)(dst + rA * CH + obase + cb) = oA;
        *(float2*)(dst + (rA + 8) * CH + obase + cb) = oB;
    }
}

// ---------------------------------------------------------------------------
// Kernel 2: attention, HEAD-SPLIT. grid (8 i-tiles, 64 b, 2 h), 256 threads.
// Score/softmax: warp owns 2 rows, in-warp softmax (no max-sub; e bounded).
// Aggregation: tf32 MMA  out_h[16x64] = alpha[16x128] @ fsrc[128x64],
//   one warp per 8-col n-tile, k = 128 within-warp, direct STG to g_part.
// smem (floats):
//   fsrc_h [128 x 64]  swizzled 16B chunks       0 .. 8192
//   fdst_h [16 x 68]   padded                 8192 .. 9280
//   alphaT [16 x 132]  tf32 bits              9280 .. 11392
//   a04    [64]                              11392 .. 11456
//   sA     [128]                             11456 .. 11584  (1.5-prescaled)
//   dA     [16]                              11584 .. 11600
// ---------------------------------------------------------------------------
#define OFF_FDST   8192
#define OFF_ALPHAT 9280
#define OFF_A04    11392
#define OFF_SA     11456
#define OFF_DA     11584
#define SM_FLOATS  11600
#define SM_BYTES   (SM_FLOATS * 4)

__global__ __launch_bounds__(256, 4) void attn_kernel(const float* __restrict__ attn_w)
{
    extern __shared__ float sm[];
    float*    fsrc_sm = sm;
    float*    fdst_sm = sm + OFF_FDST;
    unsigned* alphaT  = (unsigned*)(sm + OFF_ALPHAT);
    float*    a04     = sm + OFF_A04;
    float*    sA      = sm + OFF_SA;
    float*    dA      = sm + OFF_DA;

    const int tid = threadIdx.x;
    const int b  = blockIdx.y;
    const int i0 = blockIdx.x * TI;
    const int h  = blockIdx.z;

    ulonglong2* fs16 = (ulonglong2*)fsrc_sm;

    // ---- fill fsrc_h: 128 rows x 16 chunks (swizzled, STS.128) ----
    {
        const float4* __restrict__ g4 = (const float4*)(g_fsrc + b * WW * CH + h * 64);
        #pragma unroll
        for (int t = 0; t < 8; t++) {
            int m = tid + 256 * t;           // 2048 chunks
            int j = m >> 4, c = m & 15;
            float4 v = g4[j * 32 + c];
            *(float4*)(fsrc_sm + j * 64 + swz16(j, c) * 4) = v;
        }
    }
    // ---- fill fdst_h tile: 16 rows x 16 chunks, padded stride 68 ----
    {
        const float4* __restrict__ g4 = (const float4*)(g_fdst + (b * WW + i0) * CH + h * 64);
        int i = tid >> 4, c = tid & 15;
        *(float4*)(fdst_sm + i * 68 + c * 4) = g4[i * 32 + c];
    }
    if (tid < 64) a04[tid] = 0.4f * attn_w[h * 64 + tid];
    __syncthreads();

    // ---- per-node dots (1.5-prescaled linear leakyrelu component) ----
    if (tid < 128) {               // sA[j]
        int j = tid;
        const ulonglong2* a16 = (const ulonglong2*)a04;
        ull acc = 0ULL;
        #pragma unroll
        for (int f4 = 0; f4 < 16; f4++) {
            ulonglong2 sv = fs16[j * 16 + swz16(j, f4)];
            ulonglong2 av = a16[f4];
            acc = fma2(av.x, sv.x, acc);
            acc = fma2(av.y, sv.y, acc);
        }
        sA[j] = 1.5f * hsum2(acc);
    } else if (tid < 144) {        // dA[i]
        int il = tid - 128;
        const ulonglong2* d16 = (const ulonglong2*)(fdst_sm + il * 68);
        const ulonglong2* a16 = (const ulonglong2*)a04;
        ull acc = 0ULL;
        #pragma unroll
        for (int f4 = 0; f4 < 16; f4++) {
            ulonglong2 dv = d16[f4];
            ulonglong2 av = a16[f4];
            acc = fma2(av.x, dv.x, acc);
            acc = fma2(av.y, dv.y, acc);
        }
        dA[il] = 1.5f * hsum2(acc);
    }
    __syncthreads();

    // ---- score: warp w owns i rows {w, w+8}; lanes jt; j = jt + 32c ----
    const int jt = tid & 31;
    const int w  = tid >> 5;

    ull acc2[2][4];
    #pragma unroll
    for (int r = 0; r < 2; r++)
        #pragma unroll
        for (int c = 0; c < 4; c++) acc2[r][c] = 0ULL;

    {
        const ulonglong2* a16 = (const ulonglong2*)a04;
        #pragma unroll 4
        for (int f4 = 0; f4 < 16; f4++) {
            ulonglong2 av = a16[f4];
            ulonglong2 dv[2], sv[4];
            dv[0] = *(const ulonglong2*)(fdst_sm + w * 68 + f4 * 4);
            dv[1] = *(const ulonglong2*)(fdst_sm + (w + 8) * 68 + f4 * 4);
            int cs = swz16(jt, f4);
            #pragma unroll
            for (int c = 0; c < 4; c++)
                sv[c] = fs16[(jt + 32 * c) * 16 + cs];
            #pragma unroll
            for (int r = 0; r < 2; r++)
                #pragma unroll
                for (int c = 0; c < 4; c++) {
                    ull t0 = add2(sv[c].x, dv[r].x) & ABSMASK;
                    acc2[r][c] = fma2(av.x, t0, acc2[r][c]);
                    ull t1 = add2(sv[c].y, dv[r].y) & ABSMASK;
                    acc2[r][c] = fma2(av.y, t1, acc2[r][c]);
                }
        }
    }

    // ---- softmax over j (in-warp, no max-sub: |e| <~ 25 << 88) ----
    // write alpha as tf32 scalars into alphaT[16 x 132]
    {
        float sAv[4];
        #pragma unroll
        for (int c = 0; c < 4; c++) sAv[c] = sA[jt + 32 * c];

        #pragma unroll
        for (int r = 0; r < 2; r++) {
            int il = w + 8 * r;
            float dv = dA[il];
            float p[4], ssum = 0.0f;
            #pragma unroll
            for (int c = 0; c < 4; c++) {
                p[c] = __expf(sAv[c] + dv + hsum2(acc2[r][c]));
                ssum += p[c];
            }
            #pragma unroll
            for (int off = 16; off > 0; off >>= 1)
                ssum += __shfl_xor_sync(0xffffffffu, ssum, off);

            float inv = 1.0f / ssum;
            #pragma unroll
            for (int c = 0; c < 4; c++)
                alphaT[il * 132 + jt + 32 * c] = to_tf32(p[c] * inv);
        }
    }
    __syncthreads();

    // ---- aggregation via tf32 MMA: warp w -> n-tile cols [w*8, w*8+8) ----
    {
        const int lane = tid & 31;
        const int ly = lane >> 2;     // 0..7
        const int lx = lane & 3;      // 0..3
        const int n0 = w * 8;

        float acc[4];
        acc[0] = acc[1] = acc[2] = acc[3] = 0.0f;

        const int f  = n0 + ly;       // output feature this lane serves in B
        const int cc = f >> 2;        // 16B chunk of f
        const int fr = f & 3;

        #pragma unroll
        for (int k0 = 0; k0 < 128; k0 += 8) {
            unsigned a0 = alphaT[ly * 132 + k0 + lx];
            unsigned a1 = alphaT[(ly + 8) * 132 + k0 + lx];
            unsigned a2 = alphaT[ly * 132 + k0 + lx + 4];
            unsigned a3 = alphaT[(ly + 8) * 132 + k0 + lx + 4];
            int j0 = k0 + lx, j1 = k0 + lx + 4;
            unsigned b0 = to_tf32(fsrc_sm[j0 * 64 + swz16(j0, cc) * 4 + fr]);
            unsigned b1 = to_tf32(fsrc_sm[j1 * 64 + swz16(j1, cc) * 4 + fr]);
            asm("mma.sync.aligned.m16n8k8.row.col.f32.tf32.tf32.f32 "
                "{%0,%1,%2,%3}, {%4,%5,%6,%7}, {%8,%9}, {%0,%1,%2,%3};"
                : "+f"(acc[0]), "+f"(acc[1]), "+f"(acc[2]), "+f"(acc[3])
                : "r"(a0), "r"(a1), "r"(a2), "r"(a3), "r"(b0), "r"(b1));
        }

        // D[ly][n0+2lx..+1] = acc[0..1]; D[ly+8][...] = acc[2..3]
        float* part = g_part + h * PARTN;
        int iA = i0 + ly;
        *(float2*)(part + (b * WW + iA) * OUTF + n0 + 2 * lx) =
            make_float2(acc[0], acc[1]);
        *(float2*)(part + (b * WW + iA + 8) * OUTF + n0 + 2 * lx) =
            make_float2(acc[2], acc[3]);
    }
}

// ---------------------------------------------------------------------------
// Kernel 3: combine heads. out = 0.5 * (part0 + part1). 512 x 256 float4.
// ---------------------------------------------------------------------------
__global__ __launch_bounds__(256) void combine_kernel(float* __restrict__ out)
{
    int m = blockIdx.x * 256 + threadIdx.x;
    const float4* p0 = (const float4*)g_part;
    const float4* p1 = (const float4*)(g_part + PARTN);
    float4 a = p0[m], c = p1[m];
    float4 o;
    o.x = 0.5f * (a.x + c.x);
    o.y = 0.5f * (a.y + c.y);
    o.z = 0.5f * (a.z + c.z);
    o.w = 0.5f * (a.w + c.w);
    ((float4*)out)[m] = o;
}

// ---------------------------------------------------------------------------
extern "C" void kernel_launch(void* const* d_in, const int* in_sizes, int n_in,
                              void* d_out, int out_size)
{
    (void)in_sizes; (void)n_in; (void)out_size;
    const float* x      = (const float*)d_in[0];
    const float* w_src  = (const float*)d_in[1];
    const float* b_src  = (const float*)d_in[2];
    const float* w_dst  = (const float*)d_in[3];
    const float* b_dst  = (const float*)d_in[4];
    const float* attn_w = (const float*)d_in[5];
    float* out = (float*)d_out;

    cudaFuncSetAttribute(proj_kernel,
                         cudaFuncAttributeMaxDynamicSharedMemorySize,
                         PROJ_SM_BYTES);
    cudaFuncSetAttribute(attn_kernel,
                         cudaFuncAttributeMaxDynamicSharedMemorySize,
                         SM_BYTES);

    proj_kernel<<<dim3(4, 256), 256, PROJ_SM_BYTES>>>(x, w_src, b_src, w_dst, b_dst);
    attn_kernel<<<dim3(WW / TI, BB, 2), 256, SM_BYTES>>>(attn_w);
    combine_kernel<<<512, 256>>>(out);
}

// round 11
// speedup vs baseline: 1.1417x; 1.0285x over previous
#include <cuda_runtime.h>

#define BB 64
#define WW 128
#define FF 64
#define OUTF 64
#define CH 128
#define TI 16
#define PARTN (BB * WW * OUTF)

typedef unsigned long long ull;

// Scratch: projected features (with bias), per-head partial outputs
__device__ float g_fsrc[BB * WW * CH];
__device__ float g_fdst[BB * WW * CH];
__device__ float g_part[2 * PARTN];

// ---- packed f32x2 helpers ----
__device__ __forceinline__ ull fma2(ull a, ull b, ull c) {
    ull d; asm("fma.rn.f32x2 %0, %1, %2, %3;" : "=l"(d) : "l"(a), "l"(b), "l"(c)); return d;
}
__device__ __forceinline__ ull add2(ull a, ull b) {
    ull d; asm("add.rn.f32x2 %0, %1, %2;" : "=l"(d) : "l"(a), "l"(b)); return d;
}
__device__ __forceinline__ float lo2(ull v) { return __uint_as_float((unsigned)(v & 0xffffffffu)); }
__device__ __forceinline__ float hi2(ull v) { return __uint_as_float((unsigned)(v >> 32)); }
__device__ __forceinline__ float hsum2(ull v) { return lo2(v) + hi2(v); }
#define ABSMASK 0x7fffffff7fffffffULL

// 16B-chunk swizzle within a 64-float (16-chunk) row
__device__ __forceinline__ int swz16(int row, int c) { return (c & 8) | ((c ^ row) & 7); }

__device__ __forceinline__ unsigned to_tf32(float v) {
    unsigned o; asm("cvt.rna.tf32.f32 %0, %1;" : "=r"(o) : "f"(v)); return o;
}

// ---------------------------------------------------------------------------
// Kernel 1: projections via tf32 tensor cores, 64-row tiles (r9 config).
// C[8192 x 256] = X[8192 x 64] @ W^T + bias.
// grid (4, 128): bx = (src/dst, 64-col half), by = 64-row tile. 256 thr.
// ---------------------------------------------------------------------------
#define PROJ_SM_BYTES ((64 * 68 + 64 * 68) * 4)

__global__ __launch_bounds__(256, 4) void proj_kernel(
    const float* __restrict__ x,
    const float* __restrict__ w_src, const float* __restrict__ b_src,
    const float* __restrict__ w_dst, const float* __restrict__ b_dst)
{
    extern __shared__ unsigned psm[];
    unsigned* xs = psm;                 // 64 x 68 (tf32 bits)
    unsigned* ws = psm + 64 * 68;       // 64 x 68

    const int tid = threadIdx.x;
    const int ot = blockIdx.x;           // 0..3
    const int row0 = blockIdx.y * 64;
    const bool is_src = (ot < 2);
    const float* __restrict__ wm = is_src ? w_src : w_dst;
    const float* __restrict__ bv = is_src ? b_src : b_dst;
    const int obase = (ot & 1) * 64;

    // ---- fill (convert to tf32 once) ----
    const float4* __restrict__ x4 = (const float4*)(x + row0 * FF);
    const float4* __restrict__ w4 = (const float4*)(wm + obase * FF);
    #pragma unroll
    for (int t = 0; t < 4; t++) {        // 1024 float4 of x
        int m = tid + 256 * t;
        int r = m >> 4, c4 = m & 15;
        float4 v = x4[m];
        uint4 u;
        u.x = to_tf32(v.x); u.y = to_tf32(v.y);
        u.z = to_tf32(v.z); u.w = to_tf32(v.w);
        *(uint4*)(xs + r * 68 + c4 * 4) = u;
    }
    #pragma unroll
    for (int t = 0; t < 4; t++) {        // 1024 float4 of w
        int m = tid + 256 * t;
        int r = m >> 4, c4 = m & 15;
        float4 v = w4[m];
        uint4 u;
        u.x = to_tf32(v.x); u.y = to_tf32(v.y);
        u.z = to_tf32(v.z); u.w = to_tf32(v.w);
        *(uint4*)(ws + r * 68 + c4 * 4) = u;
    }
    __syncthreads();

    const int w    = tid >> 5;
    const int lane = tid & 31;
    const int ly = lane >> 2;     // 0..7
    const int lx = lane & 3;      // 0..3
    const int m0 = (w & 3) * 16;
    const int n0 = (w >> 2) * 32;

    float acc[4][4];
    #pragma unroll
    for (int t = 0; t < 4; t++)
        #pragma unroll
        for (int q = 0; q < 4; q++) acc[t][q] = 0.0f;

    #pragma unroll
    for (int k0 = 0; k0 < 64; k0 += 8) {
        unsigned a0 = xs[(m0 + ly) * 68 + k0 + lx];
        unsigned a1 = xs[(m0 + ly + 8) * 68 + k0 + lx];
        unsigned a2 = xs[(m0 + ly) * 68 + k0 + lx + 4];
        unsigned a3 = xs[(m0 + ly + 8) * 68 + k0 + lx + 4];
        #pragma unroll
        for (int t = 0; t < 4; t++) {
            unsigned b0 = ws[(n0 + t * 8 + ly) * 68 + k0 + lx];
            unsigned b1 = ws[(n0 + t * 8 + ly) * 68 + k0 + lx + 4];
            asm("mma.sync.aligned.m16n8k8.row.col.f32.tf32.tf32.f32 "
                "{%0,%1,%2,%3}, {%4,%5,%6,%7}, {%8,%9}, {%0,%1,%2,%3};"
                : "+f"(acc[t][0]), "+f"(acc[t][1]), "+f"(acc[t][2]), "+f"(acc[t][3])
                : "r"(a0), "r"(a1), "r"(a2), "r"(a3), "r"(b0), "r"(b1));
        }
    }

    // ---- epilogue: bias + store (STG.64 pairs) ----
    float* __restrict__ dst = is_src ? g_fsrc : g_fdst;
    #pragma unroll
    for (int t = 0; t < 4; t++) {
        int cb = n0 + t * 8 + 2 * lx;            // local col (pair base)
        float2 bias = *(const float2*)(bv + obase + cb);
        int rA = row0 + m0 + ly;
        float2 oA = make_float2(acc[t][0] + bias.x, acc[t][1] + bias.y);
        float2 oB = make_float2(acc[t][2] + bias.x, acc[t][3] + bias.y);
        *(float2*)(dst + rA * CH + obase + cb) = oA;
        *(float2*)(dst + (rA + 8) * CH + obase + cb) = oB;
    }

#if __CUDA_ARCH__ >= 900
    cudaTriggerProgrammaticLaunchCompletion();
#endif
}

// ---------------------------------------------------------------------------
// Kernel 2: attention, HEAD-SPLIT. grid (8 i-tiles, 64 b, 2 h), 256 threads.
// Score/softmax: warp owns 2 rows, in-warp softmax (no max-sub; e bounded).
// Aggregation: tf32 MMA  out_h[16x64] = alpha[16x128] @ fsrc[128x64].
// PDL: waits on proj completion only right before reading g_fsrc/g_fdst.
// ---------------------------------------------------------------------------
#define OFF_FDST   8192
#define OFF_ALPHAT 9280
#define OFF_A04    11392
#define OFF_SA     11456
#define OFF_DA     11584
#define SM_FLOATS  11600
#define SM_BYTES   (SM_FLOATS * 4)

__global__ __launch_bounds__(256, 4) void attn_kernel(const float* __restrict__ attn_w)
{
    extern __shared__ float sm[];
    float*    fsrc_sm = sm;
    float*    fdst_sm = sm + OFF_FDST;
    unsigned* alphaT  = (unsigned*)(sm + OFF_ALPHAT);
    float*    a04     = sm + OFF_A04;
    float*    sA      = sm + OFF_SA;
    float*    dA      = sm + OFF_DA;

    const int tid = threadIdx.x;
    const int b  = blockIdx.y;
    const int i0 = blockIdx.x * TI;
    const int h  = blockIdx.z;

    ulonglong2* fs16 = (ulonglong2*)fsrc_sm;

    // non-dependent input load first (overlaps with proj tail under PDL)
    if (tid < 64) a04[tid] = 0.4f * attn_w[h * 64 + tid];

#if __CUDA_ARCH__ >= 900
    cudaGridDependencySynchronize();    // proj results now visible
#endif

    // ---- fill fsrc_h: 128 rows x 16 chunks (swizzled, STS.128) ----
    {
        const float4* __restrict__ g4 = (const float4*)(g_fsrc + b * WW * CH + h * 64);
        #pragma unroll
        for (int t = 0; t < 8; t++) {
            int m = tid + 256 * t;           // 2048 chunks
            int j = m >> 4, c = m & 15;
            float4 v = g4[j * 32 + c];
            *(float4*)(fsrc_sm + j * 64 + swz16(j, c) * 4) = v;
        }
    }
    // ---- fill fdst_h tile: 16 rows x 16 chunks, padded stride 68 ----
    {
        const float4* __restrict__ g4 = (const float4*)(g_fdst + (b * WW + i0) * CH + h * 64);
        int i = tid >> 4, c = tid & 15;
        *(float4*)(fdst_sm + i * 68 + c * 4) = g4[i * 32 + c];
    }
    __syncthreads();

    // ---- per-node dots (1.5-prescaled linear leakyrelu component) ----
    if (tid < 128) {               // sA[j]
        int j = tid;
        const ulonglong2* a16 = (const ulonglong2*)a04;
        ull acc = 0ULL;
        #pragma unroll
        for (int f4 = 0; f4 < 16; f4++) {
            ulonglong2 sv = fs16[j * 16 + swz16(j, f4)];
            ulonglong2 av = a16[f4];
            acc = fma2(av.x, sv.x, acc);
            acc = fma2(av.y, sv.y, acc);
        }
        sA[j] = 1.5f * hsum2(acc);
    } else if (tid < 144) {        // dA[i]
        int il = tid - 128;
        const ulonglong2* d16 = (const ulonglong2*)(fdst_sm + il * 68);
        const ulonglong2* a16 = (const ulonglong2*)a04;
        ull acc = 0ULL;
        #pragma unroll
        for (int f4 = 0; f4 < 16; f4++) {
            ulonglong2 dv = d16[f4];
            ulonglong2 av = a16[f4];
            acc = fma2(av.x, dv.x, acc);
            acc = fma2(av.y, dv.y, acc);
        }
        dA[il] = 1.5f * hsum2(acc);
    }
    __syncthreads();

    // ---- score: warp w owns i rows {w, w+8}; lanes jt; j = jt + 32c ----
    const int jt = tid & 31;
    const int w  = tid >> 5;

    ull acc2[2][4];
    #pragma unroll
    for (int r = 0; r < 2; r++)
        #pragma unroll
        for (int c = 0; c < 4; c++) acc2[r][c] = 0ULL;

    {
        const ulonglong2* a16 = (const ulonglong2*)a04;
        #pragma unroll 4
        for (int f4 = 0; f4 < 16; f4++) {
            ulonglong2 av = a16[f4];
            ulonglong2 dv[2], sv[4];
            dv[0] = *(const ulonglong2*)(fdst_sm + w * 68 + f4 * 4);
            dv[1] = *(const ulonglong2*)(fdst_sm + (w + 8) * 68 + f4 * 4);
            int cs = swz16(jt, f4);
            #pragma unroll
            for (int c = 0; c < 4; c++)
                sv[c] = fs16[(jt + 32 * c) * 16 + cs];
            #pragma unroll
            for (int r = 0; r < 2; r++)
                #pragma unroll
                for (int c = 0; c < 4; c++) {
                    ull t0 = add2(sv[c].x, dv[r].x) & ABSMASK;
                    acc2[r][c] = fma2(av.x, t0, acc2[r][c]);
                    ull t1 = add2(sv[c].y, dv[r].y) & ABSMASK;
                    acc2[r][c] = fma2(av.y, t1, acc2[r][c]);
                }
        }
    }

    // ---- softmax over j (in-warp, no max-sub: |e| <~ 25 << 88) ----
    {
        float sAv[4];
        #pragma unroll
        for (int c = 0; c < 4; c++) sAv[c] = sA[jt + 32 * c];

        #pragma unroll
        for (int r = 0; r < 2; r++) {
            int il = w + 8 * r;
            float dv = dA[il];
            float p[4], ssum = 0.0f;
            #pragma unroll
            for (int c = 0; c < 4; c++) {
                p[c] = __expf(sAv[c] + dv + hsum2(acc2[r][c]));
                ssum += p[c];
            }
            #pragma unroll
            for (int off = 16; off > 0; off >>= 1)
                ssum += __shfl_xor_sync(0xffffffffu, ssum, off);

            float inv = 1.0f / ssum;
            #pragma unroll
            for (int c = 0; c < 4; c++)
                alphaT[il * 132 + jt + 32 * c] = to_tf32(p[c] * inv);
        }
    }
    __syncthreads();

    // ---- aggregation via tf32 MMA: warp w -> n-tile cols [w*8, w*8+8) ----
    {
        const int lane = tid & 31;
        const int ly = lane >> 2;     // 0..7
        const int lx = lane & 3;      // 0..3
        const int n0 = w * 8;

        float acc[4];
        acc[0] = acc[1] = acc[2] = acc[3] = 0.0f;

        const int f  = n0 + ly;       // output feature this lane serves in B
        const int cc = f >> 2;        // 16B chunk of f
        const int fr = f & 3;

        #pragma unroll
        for (int k0 = 0; k0 < 128; k0 += 8) {
            unsigned a0 = alphaT[ly * 132 + k0 + lx];
            unsigned a1 = alphaT[(ly + 8) * 132 + k0 + lx];
            unsigned a2 = alphaT[ly * 132 + k0 + lx + 4];
            unsigned a3 = alphaT[(ly + 8) * 132 + k0 + lx + 4];
            int j0 = k0 + lx, j1 = k0 + lx + 4;
            unsigned b0 = to_tf32(fsrc_sm[j0 * 64 + swz16(j0, cc) * 4 + fr]);
            unsigned b1 = to_tf32(fsrc_sm[j1 * 64 + swz16(j1, cc) * 4 + fr]);
            asm("mma.sync.aligned.m16n8k8.row.col.f32.tf32.tf32.f32 "
                "{%0,%1,%2,%3}, {%4,%5,%6,%7}, {%8,%9}, {%0,%1,%2,%3};"
                : "+f"(acc[0]), "+f"(acc[1]), "+f"(acc[2]), "+f"(acc[3])
                : "r"(a0), "r"(a1), "r"(a2), "r"(a3), "r"(b0), "r"(b1));
        }

        // D[ly][n0+2lx..+1] = acc[0..1]; D[ly+8][...] = acc[2..3]
        float* part = g_part + h * PARTN;
        int iA = i0 + ly;
        *(float2*)(part + (b * WW + iA) * OUTF + n0 + 2 * lx) =
            make_float2(acc[0], acc[1]);
        *(float2*)(part + (b * WW + iA + 8) * OUTF + n0 + 2 * lx) =
            make_float2(acc[2], acc[3]);
    }

#if __CUDA_ARCH__ >= 900
    cudaTriggerProgrammaticLaunchCompletion();
#endif
}

// ---------------------------------------------------------------------------
// Kernel 3: combine heads. out = 0.5 * (part0 + part1). 512 x 256 float4.
// PDL: waits on attn completion right before reading g_part.
// ---------------------------------------------------------------------------
__global__ __launch_bounds__(256) void combine_kernel(float* __restrict__ out)
{
    int m = blockIdx.x * 256 + threadIdx.x;
#if __CUDA_ARCH__ >= 900
    cudaGridDependencySynchronize();
#endif
    const float4* p0 = (const float4*)g_part;
    const float4* p1 = (const float4*)(g_part + PARTN);
    float4 a = p0[m], c = p1[m];
    float4 o;
    o.x = 0.5f * (a.x + c.x);
    o.y = 0.5f * (a.y + c.y);
    o.z = 0.5f * (a.z + c.z);
    o.w = 0.5f * (a.w + c.w);
    ((float4*)out)[m] = o;
}

// ---------------------------------------------------------------------------
extern "C" void kernel_launch(void* const* d_in, const int* in_sizes, int n_in,
                              void* d_out, int out_size)
{
    (void)in_sizes; (void)n_in; (void)out_size;
    const float* x      = (const float*)d_in[0];
    const float* w_src  = (const float*)d_in[1];
    const float* b_src  = (const float*)d_in[2];
    const float* w_dst  = (const float*)d_in[3];
    const float* b_dst  = (const float*)d_in[4];
    const float* attn_w = (const float*)d_in[5];
    float* out = (float*)d_out;

    cudaFuncSetAttribute(proj_kernel,
                         cudaFuncAttributeMaxDynamicSharedMemorySize,
                         PROJ_SM_BYTES);
    cudaFuncSetAttribute(attn_kernel,
                         cudaFuncAttributeMaxDynamicSharedMemorySize,
                         SM_BYTES);

    proj_kernel<<<dim3(4, 128), 256, PROJ_SM_BYTES>>>(x, w_src, b_src, w_dst, b_dst);

    // attn with PDL edge to proj
    {
        cudaLaunchAttribute attr[1];
        attr[0].id = cudaLaunchAttributeProgrammaticStreamSerialization;
        attr[0].val.programmaticStreamSerializationAllowed = 1;
        cudaLaunchConfig_t cfg = {};
        cfg.gridDim = dim3(WW / TI, BB, 2);
        cfg.blockDim = dim3(256, 1, 1);
        cfg.dynamicSmemBytes = SM_BYTES;
        cfg.stream = 0;
        cfg.attrs = attr;
        cfg.numAttrs = 1;
        cudaLaunchKernelEx(&cfg, attn_kernel, attn_w);
    }

    // combine with PDL edge to attn
    {
        cudaLaunchAttribute attr[1];
        attr[0].id = cudaLaunchAttributeProgrammaticStreamSerialization;
        attr[0].val.programmaticStreamSerializationAllowed = 1;
        cudaLaunchConfig_t cfg = {};
        cfg.gridDim = dim3(512, 1, 1);
        cfg.blockDim = dim3(256, 1, 1);
        cfg.dynamicSmemBytes = 0;
        cfg.stream = 0;
        cfg.attrs = attr;
        cfg.numAttrs = 1;
        cudaLaunchKernelEx(&cfg, combine_kernel, out);
    }
}

// round 13
// speedup vs baseline: 1.1709x; 1.0256x over previous
#include <cuda_runtime.h>

#define BB 64
#define WW 128
#define FF 64
#define OUTF 64
#define CH 128
#define TI 16
#define PARTN (BB * WW * OUTF)

typedef unsigned long long ull;

// Scratch: projected features (with bias; fsrc stored chunk-swizzled), partials
__device__ float g_fsrc[BB * WW * CH];
__device__ float g_fdst[BB * WW * CH];
__device__ float g_part[2 * PARTN];

// ---- packed f32x2 helpers ----
__device__ __forceinline__ ull fma2(ull a, ull b, ull c) {
    ull d; asm("fma.rn.f32x2 %0, %1, %2, %3;" : "=l"(d) : "l"(a), "l"(b), "l"(c)); return d;
}
__device__ __forceinline__ ull add2(ull a, ull b) {
    ull d; asm("add.rn.f32x2 %0, %1, %2;" : "=l"(d) : "l"(a), "l"(b)); return d;
}
__device__ __forceinline__ float lo2(ull v) { return __uint_as_float((unsigned)(v & 0xffffffffu)); }
__device__ __forceinline__ float hi2(ull v) { return __uint_as_float((unsigned)(v >> 32)); }
__device__ __forceinline__ float hsum2(ull v) { return lo2(v) + hi2(v); }
#define ABSMASK 0x7fffffff7fffffffULL

// 16B-chunk swizzle within a 64-float (16-chunk) row
__device__ __forceinline__ int swz16(int row, int c) { return (c & 8) | ((c ^ row) & 7); }

__device__ __forceinline__ unsigned to_tf32(float v) {
    unsigned o; asm("cvt.rna.tf32.f32 %0, %1;" : "=r"(o) : "f"(v)); return o;
}

__device__ __forceinline__ unsigned smem_u32(const void* p) {
    unsigned a;
    asm("{ .reg .u64 t; cvta.to.shared.u64 t, %1; cvt.u32.u64 %0, t; }"
        : "=r"(a) : "l"(p));
    return a;
}
__device__ __forceinline__ void cp_async16(unsigned dst_smem, const void* src) {
    asm volatile("cp.async.cg.shared.global [%0], [%1], 16;"
                 :: "r"(dst_smem), "l"(src) : "memory");
}
__device__ __forceinline__ void cp_async_commit_wait_all() {
    asm volatile("cp.async.commit_group;" ::: "memory");
    asm volatile("cp.async.wait_group 0;" ::: "memory");
}

// ---------------------------------------------------------------------------
// Kernel 1: projections via tf32 tensor cores, 64-row tiles (r11 fill: LDG +
// cvt.rna + STS — RNE precision). C[8192 x 256] = X[8192 x 64] @ W^T + bias.
// grid (4, 128): bx = (src/dst, 64-col half), by = 64-row tile. 256 thr.
// fsrc output is written CHUNK-SWIZZLED (attn copies it verbatim).
// ---------------------------------------------------------------------------
#define PROJ_SM_BYTES ((64 * 68 + 64 * 68) * 4)

__global__ __launch_bounds__(256, 4) void proj_kernel(
    const float* __restrict__ x,
    const float* __restrict__ w_src, const float* __restrict__ b_src,
    const float* __restrict__ w_dst, const float* __restrict__ b_dst)
{
    extern __shared__ unsigned psm[];
    unsigned* xs = psm;                 // 64 x 68 (tf32 bits, RNE)
    unsigned* ws = psm + 64 * 68;       // 64 x 68

    const int tid = threadIdx.x;
    const int ot = blockIdx.x;           // 0..3
    const int row0 = blockIdx.y * 64;
    const bool is_src = (ot < 2);
    const float* __restrict__ wm = is_src ? w_src : w_dst;
    const float* __restrict__ bv = is_src ? b_src : b_dst;
    const int obase = (ot & 1) * 64;

    // ---- fill (convert to tf32 with RNE once) ----
    const float4* __restrict__ x4 = (const float4*)(x + row0 * FF);
    const float4* __restrict__ w4 = (const float4*)(wm + obase * FF);
    #pragma unroll
    for (int t = 0; t < 4; t++) {        // 1024 float4 of x
        int m = tid + 256 * t;
        int r = m >> 4, c4 = m & 15;
        float4 v = x4[m];
        uint4 u;
        u.x = to_tf32(v.x); u.y = to_tf32(v.y);
        u.z = to_tf32(v.z); u.w = to_tf32(v.w);
        *(uint4*)(xs + r * 68 + c4 * 4) = u;
    }
    #pragma unroll
    for (int t = 0; t < 4; t++) {        // 1024 float4 of w
        int m = tid + 256 * t;
        int r = m >> 4, c4 = m & 15;
        float4 v = w4[m];
        uint4 u;
        u.x = to_tf32(v.x); u.y = to_tf32(v.y);
        u.z = to_tf32(v.z); u.w = to_tf32(v.w);
        *(uint4*)(ws + r * 68 + c4 * 4) = u;
    }
    __syncthreads();

    const int w    = tid >> 5;
    const int lane = tid & 31;
    const int ly = lane >> 2;     // 0..7
    const int lx = lane & 3;      // 0..3
    const int m0 = (w & 3) * 16;
    const int n0 = (w >> 2) * 32;

    float acc[4][4];
    #pragma unroll
    for (int t = 0; t < 4; t++)
        #pragma unroll
        for (int q = 0; q < 4; q++) acc[t][q] = 0.0f;

    #pragma unroll
    for (int k0 = 0; k0 < 64; k0 += 8) {
        unsigned a0 = xs[(m0 + ly) * 68 + k0 + lx];
        unsigned a1 = xs[(m0 + ly + 8) * 68 + k0 + lx];
        unsigned a2 = xs[(m0 + ly) * 68 + k0 + lx + 4];
        unsigned a3 = xs[(m0 + ly + 8) * 68 + k0 + lx + 4];
        #pragma unroll
        for (int t = 0; t < 4; t++) {
            unsigned b0 = ws[(n0 + t * 8 + ly) * 68 + k0 + lx];
            unsigned b1 = ws[(n0 + t * 8 + ly) * 68 + k0 + lx + 4];
            asm("mma.sync.aligned.m16n8k8.row.col.f32.tf32.tf32.f32 "
                "{%0,%1,%2,%3}, {%4,%5,%6,%7}, {%8,%9}, {%0,%1,%2,%3};"
                : "+f"(acc[t][0]), "+f"(acc[t][1]), "+f"(acc[t][2]), "+f"(acc[t][3])
                : "r"(a0), "r"(a1), "r"(a2), "r"(a3), "r"(b0), "r"(b1));
        }
    }

    // ---- epilogue: bias + store; fsrc goes out chunk-swizzled ----
    float* __restrict__ dst = is_src ? g_fsrc : g_fdst;
    #pragma unroll
    for (int t = 0; t < 4; t++) {
        int cloc = n0 + t * 8 + 2 * lx;          // local col (pair base), even
        float2 bias = *(const float2*)(bv + obase + cloc);
        int oloc = obase + cloc;                 // channel 0..127
        int rA = row0 + m0 + ly;                 // bw row (j = rA & 127)
        float2 oA = make_float2(acc[t][0] + bias.x, acc[t][1] + bias.y);
        float2 oB = make_float2(acc[t][2] + bias.x, acc[t][3] + bias.y);
        if (is_src) {
            int hh = oloc >> 6, cc = (oloc & 63) >> 2, fr = oloc & 3;
            int jA = rA & 127, jB = (rA + 8) & 127;
            *(float2*)(dst + rA * CH + hh * 64 + swz16(jA, cc) * 4 + fr) = oA;
            *(float2*)(dst + (rA + 8) * CH + hh * 64 + swz16(jB, cc) * 4 + fr) = oB;
        } else {
            *(float2*)(dst + rA * CH + oloc) = oA;
            *(float2*)(dst + (rA + 8) * CH + oloc) = oB;
        }
    }

#if __CUDA_ARCH__ >= 900
    cudaTriggerProgrammaticLaunchCompletion();
#endif
}

// ---------------------------------------------------------------------------
// Kernel 2: attention, HEAD-SPLIT. grid (8 i-tiles, 64 b, 2 h), 256 threads.
// Fill: identity cp.async (g_fsrc already swizzled). Score/softmax as r10.
// Aggregation: tf32 MMA, B-fragments via cvt.rna (RNE) from smem fp32.
// ---------------------------------------------------------------------------
#define OFF_FDST   8192
#define OFF_ALPHAT 9280
#define OFF_A04    11392
#define OFF_SA     11456
#define OFF_DA     11584
#define SM_FLOATS  11600
#define SM_BYTES   (SM_FLOATS * 4)

__global__ __launch_bounds__(256, 4) void attn_kernel(const float* __restrict__ attn_w)
{
    extern __shared__ float sm[];
    float*    fsrc_sm = sm;
    float*    fdst_sm = sm + OFF_FDST;
    unsigned* alphaT  = (unsigned*)(sm + OFF_ALPHAT);
    float*    a04     = sm + OFF_A04;
    float*    sA      = sm + OFF_SA;
    float*    dA      = sm + OFF_DA;

    const int tid = threadIdx.x;
    const int b  = blockIdx.y;
    const int i0 = blockIdx.x * TI;
    const int h  = blockIdx.z;

    ulonglong2* fs16 = (ulonglong2*)fsrc_sm;

    // non-dependent input load first (overlaps with proj tail under PDL)
    float a04v = (tid < 64) ? attn_w[h * 64 + tid] : 0.0f;

#if __CUDA_ARCH__ >= 900
    cudaGridDependencySynchronize();    // proj results now visible
#endif

    // ---- fill fsrc_h (identity copy, already swizzled) + fdst via cp.async
    {
        const float4* __restrict__ g4 = (const float4*)(g_fsrc + b * WW * CH + h * 64);
        #pragma unroll
        for (int t = 0; t < 8; t++) {
            int m = tid + 256 * t;           // 2048 chunks
            int j = m >> 4, c = m & 15;
            cp_async16(smem_u32(fsrc_sm + j * 64 + c * 4), g4 + j * 32 + c);
        }
        const float4* __restrict__ g4d = (const float4*)(g_fdst + (b * WW + i0) * CH + h * 64);
        int i = tid >> 4, c = tid & 15;
        cp_async16(smem_u32(fdst_sm + i * 68 + c * 4), g4d + i * 32 + c);
    }
    if (tid < 64) a04[tid] = 0.4f * a04v;
    cp_async_commit_wait_all();
    __syncthreads();

    // ---- per-node dots (1.5-prescaled linear leakyrelu component) ----
    if (tid < 128) {               // sA[j]
        int j = tid;
        const ulonglong2* a16 = (const ulonglong2*)a04;
        ull acc = 0ULL;
        #pragma unroll
        for (int f4 = 0; f4 < 16; f4++) {
            ulonglong2 sv = fs16[j * 16 + swz16(j, f4)];
            ulonglong2 av = a16[f4];
            acc = fma2(av.x, sv.x, acc);
            acc = fma2(av.y, sv.y, acc);
        }
        sA[j] = 1.5f * hsum2(acc);
    } else if (tid < 144) {        // dA[i]
        int il = tid - 128;
        const ulonglong2* d16 = (const ulonglong2*)(fdst_sm + il * 68);
        const ulonglong2* a16 = (const ulonglong2*)a04;
        ull acc = 0ULL;
        #pragma unroll
        for (int f4 = 0; f4 < 16; f4++) {
            ulonglong2 dv = d16[f4];
            ulonglong2 av = a16[f4];
            acc = fma2(av.x, dv.x, acc);
            acc = fma2(av.y, dv.y, acc);
        }
        dA[il] = 1.5f * hsum2(acc);
    }
    __syncthreads();

    // ---- score: warp w owns i rows {w, w+8}; lanes jt; j = jt + 32c ----
    const int jt = tid & 31;
    const int w  = tid >> 5;

    ull acc2[2][4];
    #pragma unroll
    for (int r = 0; r < 2; r++)
        #pragma unroll
        for (int c = 0; c < 4; c++) acc2[r][c] = 0ULL;

    {
        const ulonglong2* a16 = (const ulonglong2*)a04;
        #pragma unroll 4
        for (int f4 = 0; f4 < 16; f4++) {
            ulonglong2 av = a16[f4];
            ulonglong2 dv[2], sv[4];
            dv[0] = *(const ulonglong2*)(fdst_sm + w * 68 + f4 * 4);
            dv[1] = *(const ulonglong2*)(fdst_sm + (w + 8) * 68 + f4 * 4);
            int cs = swz16(jt, f4);
            #pragma unroll
            for (int c = 0; c < 4; c++)
                sv[c] = fs16[(jt + 32 * c) * 16 + cs];
            #pragma unroll
            for (int r = 0; r < 2; r++)
                #pragma unroll
                for (int c = 0; c < 4; c++) {
                    ull t0 = add2(sv[c].x, dv[r].x) & ABSMASK;
                    acc2[r][c] = fma2(av.x, t0, acc2[r][c]);
                    ull t1 = add2(sv[c].y, dv[r].y) & ABSMASK;
                    acc2[r][c] = fma2(av.y, t1, acc2[r][c]);
                }
        }
    }

    // ---- softmax over j (in-warp, no max-sub: |e| <~ 25 << 88) ----
    {
        float sAv[4];
        #pragma unroll
        for (int c = 0; c < 4; c++) sAv[c] = sA[jt + 32 * c];

        #pragma unroll
        for (int r = 0; r < 2; r++) {
            int il = w + 8 * r;
            float dv = dA[il];
            float p[4], ssum = 0.0f;
            #pragma unroll
            for (int c = 0; c < 4; c++) {
                p[c] = __expf(sAv[c] + dv + hsum2(acc2[r][c]));
                ssum += p[c];
            }
            #pragma unroll
            for (int off = 16; off > 0; off >>= 1)
                ssum += __shfl_xor_sync(0xffffffffu, ssum, off);

            float inv = 1.0f / ssum;
            #pragma unroll
            for (int c = 0; c < 4; c++)
                alphaT[il * 132 + jt + 32 * c] = to_tf32(p[c] * inv);
        }
    }
    __syncthreads();

    // ---- aggregation via tf32 MMA: warp w -> n-tile cols [w*8, w*8+8) ----
    {
        const int lane = tid & 31;
        const int ly = lane >> 2;     // 0..7
        const int lx = lane & 3;      // 0..3
        const int n0 = w * 8;

        float acc[4];
        acc[0] = acc[1] = acc[2] = acc[3] = 0.0f;

        const int f  = n0 + ly;       // output feature this lane serves in B
        const int cc = f >> 2;        // 16B chunk of f
        const int fr = f & 3;

        #pragma unroll
        for (int k0 = 0; k0 < 128; k0 += 8) {
            unsigned a0 = alphaT[ly * 132 + k0 + lx];
            unsigned a1 = alphaT[(ly + 8) * 132 + k0 + lx];
            unsigned a2 = alphaT[ly * 132 + k0 + lx + 4];
            unsigned a3 = alphaT[(ly + 8) * 132 + k0 + lx + 4];
            int j0 = k0 + lx, j1 = k0 + lx + 4;
            unsigned b0 = to_tf32(fsrc_sm[j0 * 64 + swz16(j0, cc) * 4 + fr]);
            unsigned b1 = to_tf32(fsrc_sm[j1 * 64 + swz16(j1, cc) * 4 + fr]);
            asm("mma.sync.aligned.m16n8k8.row.col.f32.tf32.tf32.f32 "
                "{%0,%1,%2,%3}, {%4,%5,%6,%7}, {%8,%9}, {%0,%1,%2,%3};"
                : "+f"(acc[0]), "+f"(acc[1]), "+f"(acc[2]), "+f"(acc[3])
                : "r"(a0), "r"(a1), "r"(a2), "r"(a3), "r"(b0), "r"(b1));
        }

        // D[ly][n0+2lx..+1] = acc[0..1]; D[ly+8][...] = acc[2..3]
        float* part = g_part + h * PARTN;
        int iA = i0 + ly;
        *(float2*)(part + (b * WW + iA) * OUTF + n0 + 2 * lx) =
            make_float2(acc[0], acc[1]);
        *(float2*)(part + (b * WW + iA + 8) * OUTF + n0 + 2 * lx) =
            make_float2(acc[2], acc[3]);
    }

#if __CUDA_ARCH__ >= 900
    cudaTriggerProgrammaticLaunchCompletion();
#endif
}

// ---------------------------------------------------------------------------
// Kernel 3: combine heads. out = 0.5 * (part0 + part1). 512 x 256 float4.
// ---------------------------------------------------------------------------
__global__ __launch_bounds__(256) void combine_kernel(float* __restrict__ out)
{
    int m = blockIdx.x * 256 + threadIdx.x;
#if __CUDA_ARCH__ >= 900
    cudaGridDependencySynchronize();
#endif
    const float4* p0 = (const float4*)g_part;
    const float4* p1 = (const float4*)(g_part + PARTN);
    float4 a = p0[m], c = p1[m];
    float4 o;
    o.x = 0.5f * (a.x + c.x);
    o.y = 0.5f * (a.y + c.y);
    o.z = 0.5f * (a.z + c.z);
    o.w = 0.5f * (a.w + c.w);
    ((float4*)out)[m] = o;
}

// ---------------------------------------------------------------------------
extern "C" void kernel_launch(void* const* d_in, const int* in_sizes, int n_in,
                              void* d_out, int out_size)
{
    (void)in_sizes; (void)n_in; (void)out_size;
    const float* x      = (const float*)d_in[0];
    const float* w_src  = (const float*)d_in[1];
    const float* b_src  = (const float*)d_in[2];
    const float* w_dst  = (const float*)d_in[3];
    const float* b_dst  = (const float*)d_in[4];
    const float* attn_w = (const float*)d_in[5];
    float* out = (float*)d_out;

    cudaFuncSetAttribute(proj_kernel,
                         cudaFuncAttributeMaxDynamicSharedMemorySize,
                         PROJ_SM_BYTES);
    cudaFuncSetAttribute(attn_kernel,
                         cudaFuncAttributeMaxDynamicSharedMemorySize,
                         SM_BYTES);

    proj_kernel<<<dim3(4, 128), 256, PROJ_SM_BYTES>>>(x, w_src, b_src, w_dst, b_dst);

    // attn with PDL edge to proj
    {
        cudaLaunchAttribute attr[1];
        attr[0].id = cudaLaunchAttributeProgrammaticStreamSerialization;
        attr[0].val.programmaticStreamSerializationAllowed = 1;
        cudaLaunchConfig_t cfg = {};
        cfg.gridDim = dim3(WW / TI, BB, 2);
        cfg.blockDim = dim3(256, 1, 1);
        cfg.dynamicSmemBytes = SM_BYTES;
        cfg.stream = 0;
        cfg.attrs = attr;
        cfg.numAttrs = 1;
        cudaLaunchKernelEx(&cfg, attn_kernel, attn_w);
    }

    // combine with PDL edge to attn
    {
        cudaLaunchAttribute attr[1];
        attr[0].id = cudaLaunchAttributeProgrammaticStreamSerialization;
        attr[0].val.programmaticStreamSerializationAllowed = 1;
        cudaLaunchConfig_t cfg = {};
        cfg.gridDim = dim3(512, 1, 1);
        cfg.blockDim = dim3(256, 1, 1);
        cfg.dynamicSmemBytes = 0;
        cfg.stream = 0;
        cfg.attrs = attr;
        cfg.numAttrs = 1;
        cudaLaunchKernelEx(&cfg, combine_kernel, out);
    }
}